// round 1
// baseline (speedup 1.0000x reference)
#include <cuda_runtime.h>
#include <math.h>

#define DIMS    1024
#define SEQ     2048
#define BATCH   2
#define NHEADS  16
#define HDIM    64
#define QKVLD   3072   // row stride of fused qkv buffer [B, N, 3*DIM]

// Scratch (allocation-free rule: __device__ globals)
__device__ float g_qkv[(size_t)BATCH * SEQ * QKVLD];   // ~50.3 MB
__device__ float g_ctx[(size_t)BATCH * SEQ * DIMS];    // ~16.8 MB

// ---------------------------------------------------------------------------
// Classic 128x128x8 fp32 SGEMM, 256 threads, 8x8 microtile (2x2 blocks of 4x4
// at offsets {0,64} so all smem fragment reads are conflict-free float4).
// Requires M%128==0, N%128==0, K%8==0 (true for all shapes here).
// ---------------------------------------------------------------------------
template <bool HAS_BIAS>
__global__ __launch_bounds__(256) void sgemm128(
    const float* __restrict__ A, const float* __restrict__ B,
    const float* __restrict__ bias, float* __restrict__ C,
    int M, int N, int K)
{
    __shared__ float As[8][128];   // As[k][m] (A tile transposed)
    __shared__ float Bs[8][128];   // Bs[k][n]

    const int tid = threadIdx.x;
    const int tx  = tid & 15;      // 0..15 (n direction)
    const int ty  = tid >> 4;      // 0..15 (m direction)
    const int m0  = blockIdx.y * 128;
    const int n0  = blockIdx.x * 128;

    const int arow = tid >> 1;            // 0..127
    const int acol = (tid & 1) * 4;       // 0 or 4
    const int brow = tid >> 5;            // 0..7
    const int bcol = (tid & 31) * 4;      // 0..124

    float acc[8][8];
#pragma unroll
    for (int i = 0; i < 8; i++)
#pragma unroll
        for (int j = 0; j < 8; j++) acc[i][j] = 0.f;

    for (int kt = 0; kt < K; kt += 8) {
        float4 av = *(const float4*)(A + (size_t)(m0 + arow) * K + kt + acol);
        As[acol + 0][arow] = av.x;
        As[acol + 1][arow] = av.y;
        As[acol + 2][arow] = av.z;
        As[acol + 3][arow] = av.w;
        float4 bv = *(const float4*)(B + (size_t)(kt + brow) * N + n0 + bcol);
        *(float4*)&Bs[brow][bcol] = bv;
        __syncthreads();

#pragma unroll
        for (int k = 0; k < 8; k++) {
            float4 a0 = *(float4*)&As[k][ty * 4];
            float4 a1 = *(float4*)&As[k][64 + ty * 4];
            float4 b0 = *(float4*)&Bs[k][tx * 4];
            float4 b1 = *(float4*)&Bs[k][64 + tx * 4];
            float af[8] = {a0.x, a0.y, a0.z, a0.w, a1.x, a1.y, a1.z, a1.w};
            float bf[8] = {b0.x, b0.y, b0.z, b0.w, b1.x, b1.y, b1.z, b1.w};
#pragma unroll
            for (int i = 0; i < 8; i++)
#pragma unroll
                for (int j = 0; j < 8; j++)
                    acc[i][j] += af[i] * bf[j];
        }
        __syncthreads();
    }

#pragma unroll
    for (int ii = 0; ii < 2; ii++)
#pragma unroll
        for (int i = 0; i < 4; i++) {
            const int r = m0 + ii * 64 + ty * 4 + i;
#pragma unroll
            for (int jj = 0; jj < 2; jj++) {
                const int cb = n0 + jj * 64 + tx * 4;
                float4 v = make_float4(acc[ii * 4 + i][jj * 4 + 0],
                                       acc[ii * 4 + i][jj * 4 + 1],
                                       acc[ii * 4 + i][jj * 4 + 2],
                                       acc[ii * 4 + i][jj * 4 + 3]);
                if (HAS_BIAS) {
                    v.x += bias[cb + 0];
                    v.y += bias[cb + 1];
                    v.z += bias[cb + 2];
                    v.w += bias[cb + 3];
                }
                *(float4*)(C + (size_t)r * N + cb) = v;
            }
        }
}

// ---------------------------------------------------------------------------
// Flash attention, fp32. One block = (batch b, head h, 64-row Q tile).
// Br=Bc=64, 256 threads as 16x16, 4x4 microtiles. Softmax stats (m, l) live
// entirely in registers; row reductions via __shfl_xor across the 16-lane tx
// group (lanes differ only in bits 0..3 -> xor masks 1,2,4,8 stay in-group).
// Q and K tiles stored k-major (transposed) with odd stride 65 so the hot-loop
// fragment loads and the transposed stores are <=2-way bank conflicted.
// V stored row-major stride 68 (float4-aligned, conflict-free).
// SCALE is folded into the Q tile at load time.
// ---------------------------------------------------------------------------
__global__ __launch_bounds__(256) void flash64(
    const float* __restrict__ qkv, float* __restrict__ ctx)
{
    extern __shared__ float sm[];
    float* Qt = sm;              // [64][65]  Qt[k*65 + m], pre-scaled
    float* Kt = Qt + 64 * 65;    // [64][65]  Kt[k*65 + n]
    float* Ps = Kt + 64 * 65;    // [64][65]  Ps[n*65 + m] (P transposed)
    float* Vs = Ps + 64 * 65;    // [64][68]  Vs[n*68 + d]

    const int tid = threadIdx.x;
    const int tx = tid & 15, ty = tid >> 4;
    const int b = blockIdx.z, h = blockIdx.y;
    const int q0 = blockIdx.x * 64;
    const float scale = 0.125f;  // 64^-0.5

    const float* Qg = qkv + (size_t)b * SEQ * QKVLD + h * HDIM;
    const float* Kg = Qg + DIMS;
    const float* Vg = Qg + 2 * DIMS;

    // Load + transpose + pre-scale Q tile (once per block)
    for (int idx = tid; idx < 64 * 16; idx += 256) {
        const int m = idx >> 4, k4 = (idx & 15) << 2;
        float4 v = *(const float4*)(Qg + (size_t)(q0 + m) * QKVLD + k4);
        Qt[(k4 + 0) * 65 + m] = v.x * scale;
        Qt[(k4 + 1) * 65 + m] = v.y * scale;
        Qt[(k4 + 2) * 65 + m] = v.z * scale;
        Qt[(k4 + 3) * 65 + m] = v.w * scale;
    }

    float o[4][4];
    float m_run[4], l_run[4];
#pragma unroll
    for (int i = 0; i < 4; i++) {
        m_run[i] = -1e30f;
        l_run[i] = 0.f;
#pragma unroll
        for (int j = 0; j < 4; j++) o[i][j] = 0.f;
    }

    for (int kv0 = 0; kv0 < SEQ; kv0 += 64) {
        __syncthreads();  // previous iteration fully done with Kt/Vs/Ps (also covers Q load on iter 0)

        // Load K (transposed) and V tiles
        for (int idx = tid; idx < 64 * 16; idx += 256) {
            const int n = idx >> 4, k4 = (idx & 15) << 2;
            float4 kvv = *(const float4*)(Kg + (size_t)(kv0 + n) * QKVLD + k4);
            Kt[(k4 + 0) * 65 + n] = kvv.x;
            Kt[(k4 + 1) * 65 + n] = kvv.y;
            Kt[(k4 + 2) * 65 + n] = kvv.z;
            Kt[(k4 + 3) * 65 + n] = kvv.w;
            float4 vv = *(const float4*)(Vg + (size_t)(kv0 + n) * QKVLD + k4);
            *(float4*)(Vs + n * 68 + k4) = vv;
        }
        __syncthreads();

        // S = (Q*scale) @ K^T   -> c[i][j], rows ty*4+i, cols tx*4+j
        float c[4][4];
#pragma unroll
        for (int i = 0; i < 4; i++)
#pragma unroll
            for (int j = 0; j < 4; j++) c[i][j] = 0.f;

#pragma unroll 8
        for (int k = 0; k < 64; k++) {
            float a_[4], b_[4];
#pragma unroll
            for (int i = 0; i < 4; i++) a_[i] = Qt[k * 65 + ty * 4 + i];
#pragma unroll
            for (int j = 0; j < 4; j++) b_[j] = Kt[k * 65 + tx * 4 + j];
#pragma unroll
            for (int i = 0; i < 4; i++)
#pragma unroll
                for (int j = 0; j < 4; j++)
                    c[i][j] += a_[i] * b_[j];
        }

        // Online softmax, all in registers
#pragma unroll
        for (int i = 0; i < 4; i++) {
            float tm = fmaxf(fmaxf(c[i][0], c[i][1]), fmaxf(c[i][2], c[i][3]));
#pragma unroll
            for (int msk = 1; msk < 16; msk <<= 1)
                tm = fmaxf(tm, __shfl_xor_sync(0xffffffffu, tm, msk));
            const float mn  = fmaxf(m_run[i], tm);
            const float fac = __expf(m_run[i] - mn);
            float rs = 0.f;
#pragma unroll
            for (int j = 0; j < 4; j++) {
                const float p = __expf(c[i][j] - mn);
                c[i][j] = p;
                rs += p;
            }
#pragma unroll
            for (int msk = 1; msk < 16; msk <<= 1)
                rs += __shfl_xor_sync(0xffffffffu, rs, msk);
            l_run[i] = l_run[i] * fac + rs;
            m_run[i] = mn;
#pragma unroll
            for (int j = 0; j < 4; j++) o[i][j] *= fac;
        }

        // Stage P transposed for the PV gemm
#pragma unroll
        for (int j = 0; j < 4; j++)
#pragma unroll
            for (int i = 0; i < 4; i++)
                Ps[(tx * 4 + j) * 65 + ty * 4 + i] = c[i][j];
        __syncthreads();

        // O += P @ V
#pragma unroll 8
        for (int n = 0; n < 64; n++) {
            float a_[4];
#pragma unroll
            for (int i = 0; i < 4; i++) a_[i] = Ps[n * 65 + ty * 4 + i];
            float4 bv = *(const float4*)(Vs + n * 68 + tx * 4);
#pragma unroll
            for (int i = 0; i < 4; i++) {
                o[i][0] += a_[i] * bv.x;
                o[i][1] += a_[i] * bv.y;
                o[i][2] += a_[i] * bv.z;
                o[i][3] += a_[i] * bv.w;
            }
        }
    }

    // Normalize and write ctx[b][q][h*64 + d]  (== transpose(0,2,1,3).reshape)
#pragma unroll
    for (int i = 0; i < 4; i++) {
        const float inv = 1.0f / l_run[i];
        float4 v = make_float4(o[i][0] * inv, o[i][1] * inv,
                               o[i][2] * inv, o[i][3] * inv);
        *(float4*)(ctx + ((size_t)b * SEQ + q0 + ty * 4 + i) * DIMS
                   + h * HDIM + tx * 4) = v;
    }
}

// ---------------------------------------------------------------------------
extern "C" void kernel_launch(void* const* d_in, const int* in_sizes, int n_in,
                              void* d_out, int out_size)
{
    const float* x      = (const float*)d_in[0];  // [2, 2048, 1024]
    const float* w_qkv  = (const float*)d_in[1];  // [1024, 3072]
    const float* w_proj = (const float*)d_in[2];  // [1024, 1024]
    const float* b_proj = (const float*)d_in[3];  // [1024]
    float* out = (float*)d_out;                   // [2, 2048, 1024]

    float *qkv, *ctx;
    cudaGetSymbolAddress((void**)&qkv, g_qkv);
    cudaGetSymbolAddress((void**)&ctx, g_ctx);

    const int M = BATCH * SEQ;  // 4096

    // 1) QKV projection: [4096,1024] @ [1024,3072]
    sgemm128<false><<<dim3(QKVLD / 128, M / 128), 256>>>(
        x, w_qkv, nullptr, qkv, M, QKVLD, DIMS);

    // 2) Flash attention
    const size_t smem = (size_t)(3 * 64 * 65 + 64 * 68) * sizeof(float); // 67328 B
    cudaFuncSetAttribute(flash64, cudaFuncAttributeMaxDynamicSharedMemorySize,
                         (int)smem);
    flash64<<<dim3(SEQ / 64, NHEADS, BATCH), 256, smem>>>(qkv, ctx);

    // 3) Output projection + bias: [4096,1024] @ [1024,1024] + b
    sgemm128<true><<<dim3(DIMS / 128, M / 128), 256>>>(
        ctx, w_proj, b_proj, out, M, DIMS, DIMS);
}

// round 5
// speedup vs baseline: 1.3431x; 1.3431x over previous
#include <cuda_runtime.h>
#include <cstdint>
#include <math.h>

#define DIMS    1024
#define SEQ     2048
#define BATCH   2
#define NHEADS  16
#define HDIM    64
#define QKVLD   3072

// ---------------------------------------------------------------------------
// Scratch (allocation-free rule: __device__ globals)
// ---------------------------------------------------------------------------
__device__ float g_qkv[(size_t)BATCH * SEQ * QKVLD];   // ~50.3 MB
__device__ float g_ctx[(size_t)BATCH * SEQ * DIMS];    // ~16.8 MB
__device__ float g_wqkvT[(size_t)QKVLD * DIMS];        // 12.6 MB  [3072][1024]
__device__ float g_wprojT[(size_t)DIMS * DIMS];        // 4.2 MB   [1024][1024]

__device__ __forceinline__ uint32_t f32_to_tf32(float f) {
    uint32_t u;
    asm("cvt.rna.tf32.f32 %0, %1;" : "=r"(u) : "f"(f));
    return u;
}

__device__ __forceinline__ void mma_tf32(float* d, const uint32_t* a, const uint32_t* b) {
    asm volatile(
        "mma.sync.aligned.m16n8k8.row.col.f32.tf32.tf32.f32 "
        "{%0,%1,%2,%3}, {%4,%5,%6,%7}, {%8,%9}, {%0,%1,%2,%3};"
        : "+f"(d[0]), "+f"(d[1]), "+f"(d[2]), "+f"(d[3])
        : "r"(a[0]), "r"(a[1]), "r"(a[2]), "r"(a[3]), "r"(b[0]), "r"(b[1]));
}

// ---------------------------------------------------------------------------
// Weight transpose: out[c][r] = in[r][c].  R, C multiples of 32.
// ---------------------------------------------------------------------------
__global__ __launch_bounds__(256) void transpose_k(
    const float* __restrict__ in, float* __restrict__ out, int R, int C)
{
    __shared__ float t[32][33];
    int x = blockIdx.x * 32 + threadIdx.x;
    int y = blockIdx.y * 32 + threadIdx.y;
#pragma unroll
    for (int j = 0; j < 32; j += 8)
        t[threadIdx.y + j][threadIdx.x] = in[(size_t)(y + j) * C + x];
    __syncthreads();
    int x2 = blockIdx.y * 32 + threadIdx.x;
    int y2 = blockIdx.x * 32 + threadIdx.y;
#pragma unroll
    for (int j = 0; j < 32; j += 8)
        out[(size_t)(y2 + j) * R + x2] = t[threadIdx.x][threadIdx.y + j];
}

// ---------------------------------------------------------------------------
// tf32 mma.sync GEMM: C[M,N] = A[M,K] @ BT[N,K]^T (+bias).
// CTA 128x128, K-chunk 16, 8 warps (2Mx4N), warp tile 64x32.
// SMEM holds tiles in *fragment order* so each thread's A frag is one LDS.128
// and B frag one LDS.64. Double-buffered, register-prefetched.
//
// A block (m16-tile mt, k8-step s): bi = mt*2+s (16 blocks, 32 lanes x 4 regs).
//   word(bi, l, reg) = (bi*32 + (l ^ ((bi&1)*2)))*4 + reg
//   element (row,k): rr=row&15, kk=k&7 -> l=(rr&7)*4+(kk&3), reg=(rr>>3)+2*(kk>>2)
// B block (n8-tile nt, step s): bi = nt*2+s (32 blocks, 32 lanes x 2 regs).
//   word(bi, l, reg) = (bi*32 + (l ^ ((bi&1)*2)))*2 + reg
//   element (n,k): nn=n&7, kk=k&7 -> l=nn*4+(kk&3), reg=kk>>2
// ---------------------------------------------------------------------------
#define CH_K 16

template <bool HAS_BIAS>
__global__ __launch_bounds__(256) void gemm_mma(
    const float* __restrict__ A, const float* __restrict__ BT,
    const float* __restrict__ bias, float* __restrict__ C,
    int M, int N, int K)
{
    __shared__ uint32_t sA[2][128 * CH_K];   // 8 KB each
    __shared__ uint32_t sB[2][128 * CH_K];

    const int tid   = threadIdx.x;
    const int lane  = tid & 31;
    const int wid   = tid >> 5;
    const int warpM = wid >> 2;      // 0..1
    const int warpN = wid & 3;       // 0..3
    const int m0 = blockIdx.y * 128;
    const int n0 = blockIdx.x * 128;

    // --- staging geometry (constant across chunks) ---
    // each thread stages 2 A float4s and 2 B float4s per chunk
    const float* agp[2];
    const float* bgp[2];
    int abase[2], bbase[2], arot[2], brot[2];
#pragma unroll
    for (int i = 0; i < 2; i++) {
        const int idx = tid + i * 256;          // 0..511
        const int row = idx >> 2;               // 0..127
        const int k0  = (idx & 3) << 2;         // 0,4,8,12
        agp[i] = A + (size_t)(m0 + row) * K + k0;
        {
            const int mt = row >> 4, rr = row & 15, s = k0 >> 3;
            const int bi = mt * 2 + s;
            const int reg = (rr >> 3) + 2 * ((k0 >> 2) & 1);
            arot[i]  = (bi & 1) * 2;
            abase[i] = (bi * 32 + (rr & 7) * 4) * 4 + reg;  // + ((q^rot)*4)
        }
        bgp[i] = BT + (size_t)(n0 + row) * K + k0;          // row doubles as n
        {
            const int nt = row >> 3, nn = row & 7, s = k0 >> 3;
            const int bi = nt * 2 + s;
            const int reg = (k0 >> 2) & 1;
            brot[i]  = (bi & 1) * 2;
            bbase[i] = (bi * 32 + nn * 4) * 2 + reg;        // + ((q^rot)*2)
        }
    }

    float acc[4][4][4];
#pragma unroll
    for (int i = 0; i < 4; i++)
#pragma unroll
        for (int j = 0; j < 4; j++)
#pragma unroll
            for (int r = 0; r < 4; r++) acc[i][j][r] = 0.f;

    float4 ra[2], rb[2];
#pragma unroll
    for (int i = 0; i < 2; i++) {
        ra[i] = *(const float4*)agp[i];
        rb[i] = *(const float4*)bgp[i];
    }
    // store chunk 0 into buffer 0
#pragma unroll
    for (int i = 0; i < 2; i++) {
        const float av[4] = {ra[i].x, ra[i].y, ra[i].z, ra[i].w};
        const float bv[4] = {rb[i].x, rb[i].y, rb[i].z, rb[i].w};
#pragma unroll
        for (int q = 0; q < 4; q++) {
            sA[0][abase[i] + ((q ^ arot[i]) << 2)] = f32_to_tf32(av[q]);
            sB[0][bbase[i] + ((q ^ brot[i]) << 1)] = f32_to_tf32(bv[q]);
        }
    }
    __syncthreads();

    const int nch = K / CH_K;
    for (int c = 0; c < nch; c++) {
        const int cur = c & 1;
        if (c + 1 < nch) {
            const int ko = (c + 1) * CH_K;
#pragma unroll
            for (int i = 0; i < 2; i++) {
                ra[i] = *(const float4*)(agp[i] + ko);
                rb[i] = *(const float4*)(bgp[i] + ko);
            }
        }

        // compute on buffer `cur`
#pragma unroll
        for (int s = 0; s < 2; s++) {
            uint32_t af[4][4];
            uint32_t bf[4][2];
#pragma unroll
            for (int i = 0; i < 4; i++) {
                const int bi = (warpM * 4 + i) * 2 + s;
                const int l  = lane ^ ((bi & 1) * 2);
                *(uint4*)af[i] = *(const uint4*)&sA[cur][(bi * 32 + l) * 4];
            }
#pragma unroll
            for (int j = 0; j < 4; j++) {
                const int bi = (warpN * 4 + j) * 2 + s;
                const int l  = lane ^ ((bi & 1) * 2);
                *(uint2*)bf[j] = *(const uint2*)&sB[cur][(bi * 32 + l) * 2];
            }
#pragma unroll
            for (int i = 0; i < 4; i++)
#pragma unroll
                for (int j = 0; j < 4; j++)
                    mma_tf32(acc[i][j], af[i], bf[j]);
        }

        if (c + 1 < nch) {
            const int nxt = cur ^ 1;
#pragma unroll
            for (int i = 0; i < 2; i++) {
                const float av[4] = {ra[i].x, ra[i].y, ra[i].z, ra[i].w};
                const float bv[4] = {rb[i].x, rb[i].y, rb[i].z, rb[i].w};
#pragma unroll
                for (int q = 0; q < 4; q++) {
                    sA[nxt][abase[i] + ((q ^ arot[i]) << 2)] = f32_to_tf32(av[q]);
                    sB[nxt][bbase[i] + ((q ^ brot[i]) << 1)] = f32_to_tf32(bv[q]);
                }
            }
        }
        __syncthreads();
    }

    // epilogue
#pragma unroll
    for (int i = 0; i < 4; i++) {
        const int row = m0 + warpM * 64 + i * 16 + (lane >> 2);
#pragma unroll
        for (int j = 0; j < 4; j++) {
            const int col = n0 + warpN * 32 + j * 8 + (lane & 3) * 2;
            float2 v0 = make_float2(acc[i][j][0], acc[i][j][1]);
            float2 v1 = make_float2(acc[i][j][2], acc[i][j][3]);
            if (HAS_BIAS) {
                const float b0 = bias[col], b1 = bias[col + 1];
                v0.x += b0; v0.y += b1;
                v1.x += b0; v1.y += b1;
            }
            *(float2*)(C + (size_t)row * N + col) = v0;
            *(float2*)(C + (size_t)(row + 8) * N + col) = v1;
        }
    }
}

// ---------------------------------------------------------------------------
// Flash attention, fp32 (unchanged — validated in R1).
// ---------------------------------------------------------------------------
__global__ __launch_bounds__(256) void flash64(
    const float* __restrict__ qkv, float* __restrict__ ctx)
{
    extern __shared__ float sm[];
    float* Qt = sm;              // [64][65]
    float* Kt = Qt + 64 * 65;    // [64][65]
    float* Ps = Kt + 64 * 65;    // [64][65]
    float* Vs = Ps + 64 * 65;    // [64][68]

    const int tid = threadIdx.x;
    const int tx = tid & 15, ty = tid >> 4;
    const int b = blockIdx.z, h = blockIdx.y;
    const int q0 = blockIdx.x * 64;
    const float scale = 0.125f;

    const float* Qg = qkv + (size_t)b * SEQ * QKVLD + h * HDIM;
    const float* Kg = Qg + DIMS;
    const float* Vg = Qg + 2 * DIMS;

    for (int idx = tid; idx < 64 * 16; idx += 256) {
        const int m = idx >> 4, k4 = (idx & 15) << 2;
        float4 v = *(const float4*)(Qg + (size_t)(q0 + m) * QKVLD + k4);
        Qt[(k4 + 0) * 65 + m] = v.x * scale;
        Qt[(k4 + 1) * 65 + m] = v.y * scale;
        Qt[(k4 + 2) * 65 + m] = v.z * scale;
        Qt[(k4 + 3) * 65 + m] = v.w * scale;
    }

    float o[4][4];
    float m_run[4], l_run[4];
#pragma unroll
    for (int i = 0; i < 4; i++) {
        m_run[i] = -1e30f;
        l_run[i] = 0.f;
#pragma unroll
        for (int j = 0; j < 4; j++) o[i][j] = 0.f;
    }

    for (int kv0 = 0; kv0 < SEQ; kv0 += 64) {
        __syncthreads();
        for (int idx = tid; idx < 64 * 16; idx += 256) {
            const int n = idx >> 4, k4 = (idx & 15) << 2;
            float4 kvv = *(const float4*)(Kg + (size_t)(kv0 + n) * QKVLD + k4);
            Kt[(k4 + 0) * 65 + n] = kvv.x;
            Kt[(k4 + 1) * 65 + n] = kvv.y;
            Kt[(k4 + 2) * 65 + n] = kvv.z;
            Kt[(k4 + 3) * 65 + n] = kvv.w;
            float4 vv = *(const float4*)(Vg + (size_t)(kv0 + n) * QKVLD + k4);
            *(float4*)(Vs + n * 68 + k4) = vv;
        }
        __syncthreads();

        float c[4][4];
#pragma unroll
        for (int i = 0; i < 4; i++)
#pragma unroll
            for (int j = 0; j < 4; j++) c[i][j] = 0.f;

#pragma unroll 8
        for (int k = 0; k < 64; k++) {
            float a_[4], b_[4];
#pragma unroll
            for (int i = 0; i < 4; i++) a_[i] = Qt[k * 65 + ty * 4 + i];
#pragma unroll
            for (int j = 0; j < 4; j++) b_[j] = Kt[k * 65 + tx * 4 + j];
#pragma unroll
            for (int i = 0; i < 4; i++)
#pragma unroll
                for (int j = 0; j < 4; j++)
                    c[i][j] += a_[i] * b_[j];
        }

#pragma unroll
        for (int i = 0; i < 4; i++) {
            float tm = fmaxf(fmaxf(c[i][0], c[i][1]), fmaxf(c[i][2], c[i][3]));
#pragma unroll
            for (int msk = 1; msk < 16; msk <<= 1)
                tm = fmaxf(tm, __shfl_xor_sync(0xffffffffu, tm, msk));
            const float mn  = fmaxf(m_run[i], tm);
            const float fac = __expf(m_run[i] - mn);
            float rs = 0.f;
#pragma unroll
            for (int j = 0; j < 4; j++) {
                const float p = __expf(c[i][j] - mn);
                c[i][j] = p;
                rs += p;
            }
#pragma unroll
            for (int msk = 1; msk < 16; msk <<= 1)
                rs += __shfl_xor_sync(0xffffffffu, rs, msk);
            l_run[i] = l_run[i] * fac + rs;
            m_run[i] = mn;
#pragma unroll
            for (int j = 0; j < 4; j++) o[i][j] *= fac;
        }

#pragma unroll
        for (int j = 0; j < 4; j++)
#pragma unroll
            for (int i = 0; i < 4; i++)
                Ps[(tx * 4 + j) * 65 + ty * 4 + i] = c[i][j];
        __syncthreads();

#pragma unroll 8
        for (int n = 0; n < 64; n++) {
            float a_[4];
#pragma unroll
            for (int i = 0; i < 4; i++) a_[i] = Ps[n * 65 + ty * 4 + i];
            float4 bv = *(const float4*)(Vs + n * 68 + tx * 4);
#pragma unroll
            for (int i = 0; i < 4; i++) {
                o[i][0] += a_[i] * bv.x;
                o[i][1] += a_[i] * bv.y;
                o[i][2] += a_[i] * bv.z;
                o[i][3] += a_[i] * bv.w;
            }
        }
    }

#pragma unroll
    for (int i = 0; i < 4; i++) {
        const float inv = 1.0f / l_run[i];
        float4 v = make_float4(o[i][0] * inv, o[i][1] * inv,
                               o[i][2] * inv, o[i][3] * inv);
        *(float4*)(ctx + ((size_t)b * SEQ + q0 + ty * 4 + i) * DIMS
                   + h * HDIM + tx * 4) = v;
    }
}

// ---------------------------------------------------------------------------
extern "C" void kernel_launch(void* const* d_in, const int* in_sizes, int n_in,
                              void* d_out, int out_size)
{
    const float* x      = (const float*)d_in[0];
    const float* w_qkv  = (const float*)d_in[1];
    const float* w_proj = (const float*)d_in[2];
    const float* b_proj = (const float*)d_in[3];
    float* out = (float*)d_out;

    float *qkv, *ctx, *wqkvT, *wprojT;
    cudaGetSymbolAddress((void**)&qkv, g_qkv);
    cudaGetSymbolAddress((void**)&ctx, g_ctx);
    cudaGetSymbolAddress((void**)&wqkvT, g_wqkvT);
    cudaGetSymbolAddress((void**)&wprojT, g_wprojT);

    const int M = BATCH * SEQ;  // 4096

    // 0) Pre-transpose weights to K-major [N][K]
    transpose_k<<<dim3(QKVLD / 32, DIMS / 32), dim3(32, 8)>>>(w_qkv, wqkvT, DIMS, QKVLD);
    transpose_k<<<dim3(DIMS / 32, DIMS / 32), dim3(32, 8)>>>(w_proj, wprojT, DIMS, DIMS);

    // 1) QKV projection (tf32 mma.sync)
    gemm_mma<false><<<dim3(QKVLD / 128, M / 128), 256>>>(
        x, wqkvT, nullptr, qkv, M, QKVLD, DIMS);

    // 2) Flash attention (fp32)
    const size_t smem = (size_t)(3 * 64 * 65 + 64 * 68) * sizeof(float);
    cudaFuncSetAttribute(flash64, cudaFuncAttributeMaxDynamicSharedMemorySize,
                         (int)smem);
    flash64<<<dim3(SEQ / 64, NHEADS, BATCH), 256, smem>>>(qkv, ctx);

    // 3) Output projection + bias (tf32 mma.sync)
    gemm_mma<true><<<dim3(DIMS / 128, M / 128), 256>>>(
        ctx, wprojT, b_proj, out, M, DIMS, DIMS);
}

// round 6
// speedup vs baseline: 1.6154x; 1.2027x over previous
#include <cuda_runtime.h>
#include <cstdint>
#include <math.h>

#define DIMS    1024
#define SEQ     2048
#define BATCH   2
#define NHEADS  16
#define HDIM    64
#define QKVLD   3072

// ---------------------------------------------------------------------------
// Scratch (allocation-free rule: __device__ globals)
// ---------------------------------------------------------------------------
__device__ float g_qkv[(size_t)BATCH * SEQ * QKVLD];   // ~50.3 MB
__device__ float g_ctx[(size_t)BATCH * SEQ * DIMS];    // ~16.8 MB
__device__ float g_wqkvT[(size_t)QKVLD * DIMS];        // 12.6 MB
__device__ float g_wprojT[(size_t)DIMS * DIMS];        // 4.2 MB

__device__ __forceinline__ uint32_t f32_to_tf32(float f) {
    uint32_t u;
    asm("cvt.rna.tf32.f32 %0, %1;" : "=r"(u) : "f"(f));
    return u;
}

__device__ __forceinline__ void mma_tf32(float* d, const uint32_t* a, const uint32_t* b) {
    asm volatile(
        "mma.sync.aligned.m16n8k8.row.col.f32.tf32.tf32.f32 "
        "{%0,%1,%2,%3}, {%4,%5,%6,%7}, {%8,%9}, {%0,%1,%2,%3};"
        : "+f"(d[0]), "+f"(d[1]), "+f"(d[2]), "+f"(d[3])
        : "r"(a[0]), "r"(a[1]), "r"(a[2]), "r"(a[3]), "r"(b[0]), "r"(b[1]));
}

// ---------------------------------------------------------------------------
// Weight transpose: out[c][r] = in[r][c].
// ---------------------------------------------------------------------------
__global__ __launch_bounds__(256) void transpose_k(
    const float* __restrict__ in, float* __restrict__ out, int R, int C)
{
    __shared__ float t[32][33];
    int x = blockIdx.x * 32 + threadIdx.x;
    int y = blockIdx.y * 32 + threadIdx.y;
#pragma unroll
    for (int j = 0; j < 32; j += 8)
        t[threadIdx.y + j][threadIdx.x] = in[(size_t)(y + j) * C + x];
    __syncthreads();
    int x2 = blockIdx.y * 32 + threadIdx.x;
    int y2 = blockIdx.x * 32 + threadIdx.y;
#pragma unroll
    for (int j = 0; j < 32; j += 8)
        out[(size_t)(y2 + j) * R + x2] = t[threadIdx.x][threadIdx.y + j];
}

// ---------------------------------------------------------------------------
// tf32 mma.sync GEMM (unchanged from R5 — validated, ~55%+ of old time cut).
// ---------------------------------------------------------------------------
#define CH_K 16

template <bool HAS_BIAS>
__global__ __launch_bounds__(256) void gemm_mma(
    const float* __restrict__ A, const float* __restrict__ BT,
    const float* __restrict__ bias, float* __restrict__ C,
    int M, int N, int K)
{
    __shared__ uint32_t sA[2][128 * CH_K];
    __shared__ uint32_t sB[2][128 * CH_K];

    const int tid   = threadIdx.x;
    const int lane  = tid & 31;
    const int wid   = tid >> 5;
    const int warpM = wid >> 2;
    const int warpN = wid & 3;
    const int m0 = blockIdx.y * 128;
    const int n0 = blockIdx.x * 128;

    const float* agp[2];
    const float* bgp[2];
    int abase[2], bbase[2], arot[2], brot[2];
#pragma unroll
    for (int i = 0; i < 2; i++) {
        const int idx = tid + i * 256;
        const int row = idx >> 2;
        const int k0  = (idx & 3) << 2;
        agp[i] = A + (size_t)(m0 + row) * K + k0;
        {
            const int mt = row >> 4, rr = row & 15, s = k0 >> 3;
            const int bi = mt * 2 + s;
            const int reg = (rr >> 3) + 2 * ((k0 >> 2) & 1);
            arot[i]  = (bi & 1) * 2;
            abase[i] = (bi * 32 + (rr & 7) * 4) * 4 + reg;
        }
        bgp[i] = BT + (size_t)(n0 + row) * K + k0;
        {
            const int nt = row >> 3, nn = row & 7, s = k0 >> 3;
            const int bi = nt * 2 + s;
            const int reg = (k0 >> 2) & 1;
            brot[i]  = (bi & 1) * 2;
            bbase[i] = (bi * 32 + nn * 4) * 2 + reg;
        }
    }

    float acc[4][4][4];
#pragma unroll
    for (int i = 0; i < 4; i++)
#pragma unroll
        for (int j = 0; j < 4; j++)
#pragma unroll
            for (int r = 0; r < 4; r++) acc[i][j][r] = 0.f;

    float4 ra[2], rb[2];
#pragma unroll
    for (int i = 0; i < 2; i++) {
        ra[i] = *(const float4*)agp[i];
        rb[i] = *(const float4*)bgp[i];
    }
#pragma unroll
    for (int i = 0; i < 2; i++) {
        const float av[4] = {ra[i].x, ra[i].y, ra[i].z, ra[i].w};
        const float bv[4] = {rb[i].x, rb[i].y, rb[i].z, rb[i].w};
#pragma unroll
        for (int q = 0; q < 4; q++) {
            sA[0][abase[i] + ((q ^ arot[i]) << 2)] = f32_to_tf32(av[q]);
            sB[0][bbase[i] + ((q ^ brot[i]) << 1)] = f32_to_tf32(bv[q]);
        }
    }
    __syncthreads();

    const int nch = K / CH_K;
    for (int c = 0; c < nch; c++) {
        const int cur = c & 1;
        if (c + 1 < nch) {
            const int ko = (c + 1) * CH_K;
#pragma unroll
            for (int i = 0; i < 2; i++) {
                ra[i] = *(const float4*)(agp[i] + ko);
                rb[i] = *(const float4*)(bgp[i] + ko);
            }
        }

#pragma unroll
        for (int s = 0; s < 2; s++) {
            uint32_t af[4][4];
            uint32_t bf[4][2];
#pragma unroll
            for (int i = 0; i < 4; i++) {
                const int bi = (warpM * 4 + i) * 2 + s;
                const int l  = lane ^ ((bi & 1) * 2);
                *(uint4*)af[i] = *(const uint4*)&sA[cur][(bi * 32 + l) * 4];
            }
#pragma unroll
            for (int j = 0; j < 4; j++) {
                const int bi = (warpN * 4 + j) * 2 + s;
                const int l  = lane ^ ((bi & 1) * 2);
                *(uint2*)bf[j] = *(const uint2*)&sB[cur][(bi * 32 + l) * 2];
            }
#pragma unroll
            for (int i = 0; i < 4; i++)
#pragma unroll
                for (int j = 0; j < 4; j++)
                    mma_tf32(acc[i][j], af[i], bf[j]);
        }

        if (c + 1 < nch) {
            const int nxt = cur ^ 1;
#pragma unroll
            for (int i = 0; i < 2; i++) {
                const float av[4] = {ra[i].x, ra[i].y, ra[i].z, ra[i].w};
                const float bv[4] = {rb[i].x, rb[i].y, rb[i].z, rb[i].w};
#pragma unroll
                for (int q = 0; q < 4; q++) {
                    sA[nxt][abase[i] + ((q ^ arot[i]) << 2)] = f32_to_tf32(av[q]);
                    sB[nxt][bbase[i] + ((q ^ brot[i]) << 1)] = f32_to_tf32(bv[q]);
                }
            }
        }
        __syncthreads();
    }

#pragma unroll
    for (int i = 0; i < 4; i++) {
        const int row = m0 + warpM * 64 + i * 16 + (lane >> 2);
#pragma unroll
        for (int j = 0; j < 4; j++) {
            const int col = n0 + warpN * 32 + j * 8 + (lane & 3) * 2;
            float2 v0 = make_float2(acc[i][j][0], acc[i][j][1]);
            float2 v1 = make_float2(acc[i][j][2], acc[i][j][3]);
            if (HAS_BIAS) {
                const float b0 = bias[col], b1 = bias[col + 1];
                v0.x += b0; v0.y += b1;
                v1.x += b0; v1.y += b1;
            }
            *(float2*)(C + (size_t)row * N + col) = v0;
            *(float2*)(C + (size_t)(row + 8) * N + col) = v1;
        }
    }
}

// ---------------------------------------------------------------------------
// Tensor-core flash attention, split-tf32 (fp32-accurate).
// 128 threads = 4 warps; Br=Bc=64; warp owns a 16-row m-tile.
// SMEM tiles in mma-fragment order, hi/lo split pairs:
//   A layout (Q / 64x64): block bi = mt*8+s (mt=row>>4, s=k>>3), 32 slots x 4 regs.
//     slot(row,k) = ((row&7)<<2) | ((k&3) ^ (((row&7)>>1)&3));   reg=((row>>3)&1)+2*((k>>2)&1)
//     word = (bi*32 + (slot ^ rot(bi)))*4 + reg;  rot(bi)=(((bi>>3)&1)<<2)|(((bi>>4)&1)<<3)
//   B layout (K: n=kv,k=hd; V: n=hd,k=kv): bi = nt*8+s, 32 slots x 2 regs.
//     slot(n,k) = ((n&7)<<2) | ((k&3) ^ (((n&7)>>1)&3));  reg=(k>>2)&1
//     word = (bi*32 + (slot ^ rot(bi)))*2 + reg
// Consumer lane c reads slot ((c>>2)<<2)|((c&3)^((c>>3)&3)) ^ rot — a lane
// permutation, so frag loads are conflict-free; staging stores are <=2-way.
// P (post-softmax) converted to A-frags in-register via shfl.idx.
// ---------------------------------------------------------------------------
__global__ __launch_bounds__(128) void flash_mma(
    const float* __restrict__ qkv, float* __restrict__ ctx)
{
    extern __shared__ uint32_t fsm[];
    uint32_t* sQh = fsm;
    uint32_t* sQl = fsm + 4096;
    uint32_t* sKh = fsm + 8192;
    uint32_t* sKl = fsm + 12288;
    uint32_t* sVh = fsm + 16384;
    uint32_t* sVl = fsm + 20480;   // total 24576 words = 96 KB

    const int tid  = threadIdx.x;
    const int lane = tid & 31;
    const int wid  = tid >> 5;
    const int b = blockIdx.z, h = blockIdx.y;
    const int q0 = blockIdx.x * 64;

    const float* Qg = qkv + (size_t)b * SEQ * QKVLD + h * HDIM;
    const float* Kg = Qg + DIMS;
    const float* Vg = Qg + 2 * DIMS;

    // consumer fragment slot + per-warp A rot (bi>>3 == wid for s<8)
    const int slotC = ((lane >> 2) << 2) | ((lane & 3) ^ ((lane >> 3) & 3));
    const int aoff  = slotC ^ (((wid & 1) << 2) | (((wid >> 1) & 1) << 3));
    int boff[8];
#pragma unroll
    for (int nt = 0; nt < 8; nt++)
        boff[nt] = slotC ^ (((nt & 1) << 2) | (((nt >> 1) & 1) << 3));

    // ---- stage Q (scaled by 0.125, hi/lo split) ----
#pragma unroll
    for (int i = 0; i < 8; i++) {
        const int idx = tid + i * 128;
        const int row = idx & 63, k0 = (idx >> 6) * 4;
        float4 v = *(const float4*)(Qg + (size_t)(q0 + row) * QKVLD + k0);
        const float vv[4] = {v.x, v.y, v.z, v.w};
        const int mt = row >> 4;
        const int rbase = (row >> 3) & 1;
#pragma unroll
        for (int q = 0; q < 4; q++) {
            const int k = k0 + q;
            const int bi = mt * 8 + (k >> 3);
            const int rot = (((bi >> 3) & 1) << 2) | (((bi >> 4) & 1) << 3);
            const int slot = ((row & 7) << 2) | ((k & 3) ^ (((row & 7) >> 1) & 3));
            const int w = (bi * 32 + (slot ^ rot)) * 4 + rbase + 2 * ((k >> 2) & 1);
            const float x = vv[q] * 0.125f;
            const uint32_t hi = f32_to_tf32(x);
            sQh[w] = hi;
            sQl[w] = f32_to_tf32(x - __uint_as_float(hi));
        }
    }

    float oacc[8][4];
    float m_run[2], l_run[2];
#pragma unroll
    for (int nt = 0; nt < 8; nt++)
#pragma unroll
        for (int r = 0; r < 4; r++) oacc[nt][r] = 0.f;
    m_run[0] = m_run[1] = -1e30f;
    l_run[0] = l_run[1] = 0.f;

    for (int kv0 = 0; kv0 < SEQ; kv0 += 64) {
        __syncthreads();  // prior iteration done reading sK/sV (covers Q on iter 0)

        // ---- stage K (n=kv, k=hd) ----
#pragma unroll
        for (int i = 0; i < 8; i++) {
            const int idx = tid + i * 128;
            const int n = idx & 63, k0 = (idx >> 6) * 4;
            float4 v = *(const float4*)(Kg + (size_t)(kv0 + n) * QKVLD + k0);
            const float vv[4] = {v.x, v.y, v.z, v.w};
#pragma unroll
            for (int q = 0; q < 4; q++) {
                const int k = k0 + q;
                const int bi = (n >> 3) * 8 + (k >> 3);
                const int rot = (((bi >> 3) & 1) << 2) | (((bi >> 4) & 1) << 3);
                const int slot = ((n & 7) << 2) | ((k & 3) ^ (((n & 7) >> 1) & 3));
                const int w = (bi * 32 + (slot ^ rot)) * 2 + ((k >> 2) & 1);
                const uint32_t hi = f32_to_tf32(vv[q]);
                sKh[w] = hi;
                sKl[w] = f32_to_tf32(vv[q] - __uint_as_float(hi));
            }
        }
        // ---- stage V (n=hd, k=kv) ----
#pragma unroll
        for (int i = 0; i < 8; i++) {
            const int idx = tid + i * 128;
            const int hd4 = idx & 15, kv = idx >> 4;   // kv 0..63
            float4 v = *(const float4*)(Vg + (size_t)(kv0 + kv) * QKVLD + hd4 * 4);
            const float vv[4] = {v.x, v.y, v.z, v.w};
            const int reg = (kv >> 2) & 1;
#pragma unroll
            for (int q = 0; q < 4; q++) {
                const int n = hd4 * 4 + q;
                const int bi = (n >> 3) * 8 + (kv >> 3);
                const int rot = (((bi >> 3) & 1) << 2) | (((bi >> 4) & 1) << 3);
                const int slot = ((n & 7) << 2) | ((kv & 3) ^ (((n & 7) >> 1) & 3));
                const int w = (bi * 32 + (slot ^ rot)) * 2 + reg;
                const uint32_t hi = f32_to_tf32(vv[q]);
                sVh[w] = hi;
                sVl[w] = f32_to_tf32(vv[q] - __uint_as_float(hi));
            }
        }
        __syncthreads();

        // ---- S = (Q*scale) @ K^T (split: hh + hl + lh) ----
        float sf[8][4];
#pragma unroll
        for (int nt = 0; nt < 8; nt++)
#pragma unroll
            for (int r = 0; r < 4; r++) sf[nt][r] = 0.f;

#pragma unroll
        for (int s = 0; s < 8; s++) {
            uint32_t aH[4], aL[4];
            *(uint4*)aH = *(const uint4*)&sQh[((wid * 8 + s) * 32 + aoff) * 4];
            *(uint4*)aL = *(const uint4*)&sQl[((wid * 8 + s) * 32 + aoff) * 4];
#pragma unroll
            for (int nt = 0; nt < 8; nt++) {
                uint32_t bH[2], bL[2];
                *(uint2*)bH = *(const uint2*)&sKh[((nt * 8 + s) * 32 + boff[nt]) * 2];
                *(uint2*)bL = *(const uint2*)&sKl[((nt * 8 + s) * 32 + boff[nt]) * 2];
                mma_tf32(sf[nt], aH, bH);
                mma_tf32(sf[nt], aH, bL);
                mma_tf32(sf[nt], aL, bH);
            }
        }

        // ---- online softmax on fragments (rows: lane>>2, +8) ----
#pragma unroll
        for (int hf = 0; hf < 2; hf++) {
            float tm = -1e30f;
#pragma unroll
            for (int nt = 0; nt < 8; nt++)
                tm = fmaxf(tm, fmaxf(sf[nt][hf * 2], sf[nt][hf * 2 + 1]));
            tm = fmaxf(tm, __shfl_xor_sync(0xffffffffu, tm, 1));
            tm = fmaxf(tm, __shfl_xor_sync(0xffffffffu, tm, 2));
            const float mn  = fmaxf(m_run[hf], tm);
            const float fac = __expf(m_run[hf] - mn);
            float sum = 0.f;
#pragma unroll
            for (int nt = 0; nt < 8; nt++) {
#pragma unroll
                for (int j = 0; j < 2; j++) {
                    const float p = __expf(sf[nt][hf * 2 + j] - mn);
                    sf[nt][hf * 2 + j] = p;
                    sum += p;
                }
            }
            sum += __shfl_xor_sync(0xffffffffu, sum, 1);
            sum += __shfl_xor_sync(0xffffffffu, sum, 2);
            l_run[hf] = l_run[hf] * fac + sum;
            m_run[hf] = mn;
#pragma unroll
            for (int nt = 0; nt < 8; nt++) {
                oacc[nt][hf * 2]     *= fac;
                oacc[nt][hf * 2 + 1] *= fac;
            }
        }

        // ---- O += P @ V (P split in-register, shfl to A-frag layout) ----
        const int src0 = (lane & ~3) | ((lane & 3) >> 1);
        const int src2 = src0 + 2;
        const bool par = lane & 1;
#pragma unroll
        for (int s = 0; s < 8; s++) {
            uint32_t pH[4], pL[4];
#pragma unroll
            for (int r = 0; r < 4; r++) {
                pH[r] = f32_to_tf32(sf[s][r]);
                pL[r] = f32_to_tf32(sf[s][r] - __uint_as_float(pH[r]));
            }
            uint32_t aH[4], aL[4];
            {
                uint32_t u0, u1;
                u0 = __shfl_sync(0xffffffffu, pH[0], src0);
                u1 = __shfl_sync(0xffffffffu, pH[1], src0);
                aH[0] = par ? u1 : u0;
                u0 = __shfl_sync(0xffffffffu, pH[2], src0);
                u1 = __shfl_sync(0xffffffffu, pH[3], src0);
                aH[1] = par ? u1 : u0;
                u0 = __shfl_sync(0xffffffffu, pH[0], src2);
                u1 = __shfl_sync(0xffffffffu, pH[1], src2);
                aH[2] = par ? u1 : u0;
                u0 = __shfl_sync(0xffffffffu, pH[2], src2);
                u1 = __shfl_sync(0xffffffffu, pH[3], src2);
                aH[3] = par ? u1 : u0;
                u0 = __shfl_sync(0xffffffffu, pL[0], src0);
                u1 = __shfl_sync(0xffffffffu, pL[1], src0);
                aL[0] = par ? u1 : u0;
                u0 = __shfl_sync(0xffffffffu, pL[2], src0);
                u1 = __shfl_sync(0xffffffffu, pL[3], src0);
                aL[1] = par ? u1 : u0;
                u0 = __shfl_sync(0xffffffffu, pL[0], src2);
                u1 = __shfl_sync(0xffffffffu, pL[1], src2);
                aL[2] = par ? u1 : u0;
                u0 = __shfl_sync(0xffffffffu, pL[2], src2);
                u1 = __shfl_sync(0xffffffffu, pL[3], src2);
                aL[3] = par ? u1 : u0;
            }
#pragma unroll
            for (int nt = 0; nt < 8; nt++) {
                uint32_t vH[2], vL[2];
                *(uint2*)vH = *(const uint2*)&sVh[((nt * 8 + s) * 32 + boff[nt]) * 2];
                *(uint2*)vL = *(const uint2*)&sVl[((nt * 8 + s) * 32 + boff[nt]) * 2];
                mma_tf32(oacc[nt], aH, vH);
                mma_tf32(oacc[nt], aH, vL);
                mma_tf32(oacc[nt], aL, vH);
            }
        }
    }

    // ---- normalize + write ctx[b][q][h*64 + d] ----
    const float inv0 = 1.0f / l_run[0];
    const float inv1 = 1.0f / l_run[1];
    const int row0 = q0 + wid * 16 + (lane >> 2);
#pragma unroll
    for (int nt = 0; nt < 8; nt++) {
        const int col = h * HDIM + nt * 8 + 2 * (lane & 3);
        *(float2*)(ctx + ((size_t)b * SEQ + row0) * DIMS + col) =
            make_float2(oacc[nt][0] * inv0, oacc[nt][1] * inv0);
        *(float2*)(ctx + ((size_t)b * SEQ + row0 + 8) * DIMS + col) =
            make_float2(oacc[nt][2] * inv1, oacc[nt][3] * inv1);
    }
}

// ---------------------------------------------------------------------------
extern "C" void kernel_launch(void* const* d_in, const int* in_sizes, int n_in,
                              void* d_out, int out_size)
{
    const float* x      = (const float*)d_in[0];
    const float* w_qkv  = (const float*)d_in[1];
    const float* w_proj = (const float*)d_in[2];
    const float* b_proj = (const float*)d_in[3];
    float* out = (float*)d_out;

    float *qkv, *ctx, *wqkvT, *wprojT;
    cudaGetSymbolAddress((void**)&qkv, g_qkv);
    cudaGetSymbolAddress((void**)&ctx, g_ctx);
    cudaGetSymbolAddress((void**)&wqkvT, g_wqkvT);
    cudaGetSymbolAddress((void**)&wprojT, g_wprojT);

    const int M = BATCH * SEQ;  // 4096

    // 0) Pre-transpose weights to K-major [N][K]
    transpose_k<<<dim3(QKVLD / 32, DIMS / 32), dim3(32, 8)>>>(w_qkv, wqkvT, DIMS, QKVLD);
    transpose_k<<<dim3(DIMS / 32, DIMS / 32), dim3(32, 8)>>>(w_proj, wprojT, DIMS, DIMS);

    // 1) QKV projection (tf32 mma.sync)
    gemm_mma<false><<<dim3(QKVLD / 128, M / 128), 256>>>(
        x, wqkvT, nullptr, qkv, M, QKVLD, DIMS);

    // 2) Flash attention (split-tf32 tensor cores)
    const int fsmem = 24576 * 4;   // 96 KB
    cudaFuncSetAttribute(flash_mma, cudaFuncAttributeMaxDynamicSharedMemorySize,
                         fsmem);
    flash_mma<<<dim3(SEQ / 64, NHEADS, BATCH), 128, fsmem>>>(qkv, ctx);

    // 3) Output projection + bias (tf32 mma.sync)
    gemm_mma<true><<<dim3(DIMS / 128, M / 128), 256>>>(
        ctx, wprojT, b_proj, out, M, DIMS, DIMS);
}

// round 8
// speedup vs baseline: 1.6874x; 1.0446x over previous
#include <cuda_runtime.h>
#include <cstdint>
#include <math.h>

#define DIMS    1024
#define SEQ     2048
#define BATCH   2
#define NHEADS  16
#define HDIM    64
#define QKVLD   3072

// ---------------------------------------------------------------------------
// Scratch (allocation-free rule: __device__ globals)
// ---------------------------------------------------------------------------
__device__ float g_qkv[(size_t)BATCH * SEQ * QKVLD];
__device__ float g_ctx[(size_t)BATCH * SEQ * DIMS];
__device__ float g_wqkvT[(size_t)QKVLD * DIMS];
__device__ float g_wprojT[(size_t)DIMS * DIMS];

__device__ __forceinline__ uint32_t f32_to_tf32(float f) {
    uint32_t u;
    asm("cvt.rna.tf32.f32 %0, %1;" : "=r"(u) : "f"(f));
    return u;
}

__device__ __forceinline__ void mma_tf32(float* d, const uint32_t* a, const uint32_t* b) {
    asm volatile(
        "mma.sync.aligned.m16n8k8.row.col.f32.tf32.tf32.f32 "
        "{%0,%1,%2,%3}, {%4,%5,%6,%7}, {%8,%9}, {%0,%1,%2,%3};"
        : "+f"(d[0]), "+f"(d[1]), "+f"(d[2]), "+f"(d[3])
        : "r"(a[0]), "r"(a[1]), "r"(a[2]), "r"(a[3]), "r"(b[0]), "r"(b[1]));
}

// ---------------------------------------------------------------------------
// Weight transpose (unchanged).
// ---------------------------------------------------------------------------
__global__ __launch_bounds__(256) void transpose_k(
    const float* __restrict__ in, float* __restrict__ out, int R, int C)
{
    __shared__ float t[32][33];
    int x = blockIdx.x * 32 + threadIdx.x;
    int y = blockIdx.y * 32 + threadIdx.y;
#pragma unroll
    for (int j = 0; j < 32; j += 8)
        t[threadIdx.y + j][threadIdx.x] = in[(size_t)(y + j) * C + x];
    __syncthreads();
    int x2 = blockIdx.y * 32 + threadIdx.x;
    int y2 = blockIdx.x * 32 + threadIdx.y;
#pragma unroll
    for (int j = 0; j < 32; j += 8)
        out[(size_t)(y2 + j) * R + x2] = t[threadIdx.x][threadIdx.y + j];
}

// ---------------------------------------------------------------------------
// tf32 mma.sync GEMM (unchanged — validated).
// ---------------------------------------------------------------------------
#define CH_K 16

template <bool HAS_BIAS>
__global__ __launch_bounds__(256) void gemm_mma(
    const float* __restrict__ A, const float* __restrict__ BT,
    const float* __restrict__ bias, float* __restrict__ C,
    int M, int N, int K)
{
    __shared__ uint32_t sA[2][128 * CH_K];
    __shared__ uint32_t sB[2][128 * CH_K];

    const int tid   = threadIdx.x;
    const int lane  = tid & 31;
    const int wid   = tid >> 5;
    const int warpM = wid >> 2;
    const int warpN = wid & 3;
    const int m0 = blockIdx.y * 128;
    const int n0 = blockIdx.x * 128;

    const float* agp[2];
    const float* bgp[2];
    int abase[2], bbase[2], arot[2], brot[2];
#pragma unroll
    for (int i = 0; i < 2; i++) {
        const int idx = tid + i * 256;
        const int row = idx >> 2;
        const int k0  = (idx & 3) << 2;
        agp[i] = A + (size_t)(m0 + row) * K + k0;
        {
            const int mt = row >> 4, rr = row & 15, s = k0 >> 3;
            const int bi = mt * 2 + s;
            const int reg = (rr >> 3) + 2 * ((k0 >> 2) & 1);
            arot[i]  = (bi & 1) * 2;
            abase[i] = (bi * 32 + (rr & 7) * 4) * 4 + reg;
        }
        bgp[i] = BT + (size_t)(n0 + row) * K + k0;
        {
            const int nt = row >> 3, nn = row & 7, s = k0 >> 3;
            const int bi = nt * 2 + s;
            const int reg = (k0 >> 2) & 1;
            brot[i]  = (bi & 1) * 2;
            bbase[i] = (bi * 32 + nn * 4) * 2 + reg;
        }
    }

    float acc[4][4][4];
#pragma unroll
    for (int i = 0; i < 4; i++)
#pragma unroll
        for (int j = 0; j < 4; j++)
#pragma unroll
            for (int r = 0; r < 4; r++) acc[i][j][r] = 0.f;

    float4 ra[2], rb[2];
#pragma unroll
    for (int i = 0; i < 2; i++) {
        ra[i] = *(const float4*)agp[i];
        rb[i] = *(const float4*)bgp[i];
    }
#pragma unroll
    for (int i = 0; i < 2; i++) {
        const float av[4] = {ra[i].x, ra[i].y, ra[i].z, ra[i].w};
        const float bv[4] = {rb[i].x, rb[i].y, rb[i].z, rb[i].w};
#pragma unroll
        for (int q = 0; q < 4; q++) {
            sA[0][abase[i] + ((q ^ arot[i]) << 2)] = f32_to_tf32(av[q]);
            sB[0][bbase[i] + ((q ^ brot[i]) << 1)] = f32_to_tf32(bv[q]);
        }
    }
    __syncthreads();

    const int nch = K / CH_K;
    for (int c = 0; c < nch; c++) {
        const int cur = c & 1;
        if (c + 1 < nch) {
            const int ko = (c + 1) * CH_K;
#pragma unroll
            for (int i = 0; i < 2; i++) {
                ra[i] = *(const float4*)(agp[i] + ko);
                rb[i] = *(const float4*)(bgp[i] + ko);
            }
        }

#pragma unroll
        for (int s = 0; s < 2; s++) {
            uint32_t af[4][4];
            uint32_t bf[4][2];
#pragma unroll
            for (int i = 0; i < 4; i++) {
                const int bi = (warpM * 4 + i) * 2 + s;
                const int l  = lane ^ ((bi & 1) * 2);
                *(uint4*)af[i] = *(const uint4*)&sA[cur][(bi * 32 + l) * 4];
            }
#pragma unroll
            for (int j = 0; j < 4; j++) {
                const int bi = (warpN * 4 + j) * 2 + s;
                const int l  = lane ^ ((bi & 1) * 2);
                *(uint2*)bf[j] = *(const uint2*)&sB[cur][(bi * 32 + l) * 2];
            }
#pragma unroll
            for (int i = 0; i < 4; i++)
#pragma unroll
                for (int j = 0; j < 4; j++)
                    mma_tf32(acc[i][j], af[i], bf[j]);
        }

        if (c + 1 < nch) {
            const int nxt = cur ^ 1;
#pragma unroll
            for (int i = 0; i < 2; i++) {
                const float av[4] = {ra[i].x, ra[i].y, ra[i].z, ra[i].w};
                const float bv[4] = {rb[i].x, rb[i].y, rb[i].z, rb[i].w};
#pragma unroll
                for (int q = 0; q < 4; q++) {
                    sA[nxt][abase[i] + ((q ^ arot[i]) << 2)] = f32_to_tf32(av[q]);
                    sB[nxt][bbase[i] + ((q ^ brot[i]) << 1)] = f32_to_tf32(bv[q]);
                }
            }
        }
        __syncthreads();
    }

#pragma unroll
    for (int i = 0; i < 4; i++) {
        const int row = m0 + warpM * 64 + i * 16 + (lane >> 2);
#pragma unroll
        for (int j = 0; j < 4; j++) {
            const int col = n0 + warpN * 32 + j * 8 + (lane & 3) * 2;
            float2 v0 = make_float2(acc[i][j][0], acc[i][j][1]);
            float2 v1 = make_float2(acc[i][j][2], acc[i][j][3]);
            if (HAS_BIAS) {
                const float b0 = bias[col], b1 = bias[col + 1];
                v0.x += b0; v0.y += b1;
                v1.x += b0; v1.y += b1;
            }
            *(float2*)(C + (size_t)row * N + col) = v0;
            *(float2*)(C + (size_t)(row + 8) * N + col) = v1;
        }
    }
}

// ---------------------------------------------------------------------------
// Tensor-core flash attention, split-tf32, Br=64 Bc=32.
// 64 KB smem/CTA -> 3 CTAs/SM (12 warps, 3/SMSP) for latency hiding.
// Fragment-order hi/lo SMEM layouts (same permutation family as R6):
//   Q: bi = mt*8 + s (mt=row>>4, s=k>>3), 32 blocks x 32 slots x 4 regs
//   K: bi = (kv>>3)*8 + (hd>>3)            32 blocks x 32 slots x 2 regs
//   V: bi = (hd>>3)*4 + (kv>>3)            32 blocks x 32 slots x 2 regs
//   slot(r,k) = ((r&7)<<2) | ((k&3) ^ (((r&7)>>1)&3))
//   rot(bi)   = (((bi>>3)&1)<<2) | (((bi>>4)&1)<<3)
// ---------------------------------------------------------------------------
__global__ __launch_bounds__(128, 3) void flash_mma(
    const float* __restrict__ qkv, float* __restrict__ ctx)
{
    extern __shared__ uint32_t fsm[];
    uint32_t* sQh = fsm;             // 4096
    uint32_t* sQl = fsm + 4096;      // 4096
    uint32_t* sKh = fsm + 8192;      // 2048
    uint32_t* sKl = fsm + 10240;     // 2048
    uint32_t* sVh = fsm + 12288;     // 2048
    uint32_t* sVl = fsm + 14336;     // 2048  -> 16384 words = 64 KB

    const int tid  = threadIdx.x;
    const int lane = tid & 31;
    const int wid  = tid >> 5;
    const int b = blockIdx.z, h = blockIdx.y;
    const int q0 = blockIdx.x * 64;

    const float* Qg = qkv + (size_t)b * SEQ * QKVLD + h * HDIM;
    const float* Kg = Qg + DIMS;
    const float* Vg = Qg + 2 * DIMS;

    const int slotC = ((lane >> 2) << 2) | ((lane & 3) ^ ((lane >> 3) & 3));
    // A-frag offset: bi = wid*8+s -> bi>>3 = wid, bi>>4 = wid>>1 (s<8)
    const int aoff  = slotC ^ (((wid & 1) << 2) | (((wid >> 1) & 1) << 3));
    // K B-frag: bi = nt*8+s, nt<4 -> bi>>3 = nt, bi>>4 = nt>>1
    int boff[4];
#pragma unroll
    for (int nt = 0; nt < 4; nt++)
        boff[nt] = slotC ^ (((nt & 1) << 2) | (((nt >> 1) & 1) << 3));
    // V B-frag: bi = ntd*4+s (s<4) -> bi>>3 = ntd>>1, bi>>4 = ntd>>2
    int voff[8];
#pragma unroll
    for (int ntd = 0; ntd < 8; ntd++)
        voff[ntd] = slotC ^ ((((ntd >> 1) & 1) << 2) | (((ntd >> 2) & 1) << 3));

    // ---- stage Q (scaled, hi/lo) : 64x64, 8 float4/thread ----
#pragma unroll
    for (int i = 0; i < 8; i++) {
        const int idx = tid + i * 128;
        const int row = idx & 63, k0 = (idx >> 6) * 4;
        float4 v = *(const float4*)(Qg + (size_t)(q0 + row) * QKVLD + k0);
        const float vv[4] = {v.x, v.y, v.z, v.w};
        const int mt = row >> 4;
        const int rbase = (row >> 3) & 1;
#pragma unroll
        for (int q = 0; q < 4; q++) {
            const int k = k0 + q;
            const int bi = mt * 8 + (k >> 3);
            const int rot = (((bi >> 3) & 1) << 2) | (((bi >> 4) & 1) << 3);
            const int slot = ((row & 7) << 2) | ((k & 3) ^ (((row & 7) >> 1) & 3));
            const int w = (bi * 32 + (slot ^ rot)) * 4 + rbase + 2 * ((k >> 2) & 1);
            const float x = vv[q] * 0.125f;
            const uint32_t hi = f32_to_tf32(x);
            sQh[w] = hi;
            sQl[w] = f32_to_tf32(x - __uint_as_float(hi));
        }
    }

    float oacc[8][4];
    float m_run[2], l_run[2];
#pragma unroll
    for (int nt = 0; nt < 8; nt++)
#pragma unroll
        for (int r = 0; r < 4; r++) oacc[nt][r] = 0.f;
    m_run[0] = m_run[1] = -1e30f;
    l_run[0] = l_run[1] = 0.f;

    for (int kv0 = 0; kv0 < SEQ; kv0 += 32) {
        __syncthreads();

        // ---- stage K: 32 kv-rows x 64 hd, 4 float4/thread ----
#pragma unroll
        for (int i = 0; i < 4; i++) {
            const int idx = tid + i * 128;
            const int n = idx & 31, k0 = (idx >> 5) * 4;
            float4 v = *(const float4*)(Kg + (size_t)(kv0 + n) * QKVLD + k0);
            const float vv[4] = {v.x, v.y, v.z, v.w};
#pragma unroll
            for (int q = 0; q < 4; q++) {
                const int k = k0 + q;
                const int bi = (n >> 3) * 8 + (k >> 3);
                const int rot = (((bi >> 3) & 1) << 2) | (((bi >> 4) & 1) << 3);
                const int slot = ((n & 7) << 2) | ((k & 3) ^ (((n & 7) >> 1) & 3));
                const int w = (bi * 32 + (slot ^ rot)) * 2 + ((k >> 2) & 1);
                const uint32_t hi = f32_to_tf32(vv[q]);
                sKh[w] = hi;
                sKl[w] = f32_to_tf32(vv[q] - __uint_as_float(hi));
            }
        }
        // ---- stage V: 32 kv-rows x 64 hd (n=hd, k=kv), 4 float4/thread ----
#pragma unroll
        for (int i = 0; i < 4; i++) {
            const int idx = tid + i * 128;
            const int hd4 = idx & 15, kv = idx >> 4;   // kv 0..31
            float4 v = *(const float4*)(Vg + (size_t)(kv0 + kv) * QKVLD + hd4 * 4);
            const float vv[4] = {v.x, v.y, v.z, v.w};
            const int reg = (kv >> 2) & 1;
#pragma unroll
            for (int q = 0; q < 4; q++) {
                const int n = hd4 * 4 + q;
                const int bi = (n >> 3) * 4 + (kv >> 3);
                const int rot = (((bi >> 3) & 1) << 2) | (((bi >> 4) & 1) << 3);
                const int slot = ((n & 7) << 2) | ((kv & 3) ^ (((n & 7) >> 1) & 3));
                const int w = (bi * 32 + (slot ^ rot)) * 2 + reg;
                const uint32_t hi = f32_to_tf32(vv[q]);
                sVh[w] = hi;
                sVl[w] = f32_to_tf32(vv[q] - __uint_as_float(hi));
            }
        }
        __syncthreads();

        // ---- S = (Q*scale) @ K^T : 8 hd-octets x 4 kv-tiles, 3-term split ----
        float sf[4][4];
#pragma unroll
        for (int nt = 0; nt < 4; nt++)
#pragma unroll
            for (int r = 0; r < 4; r++) sf[nt][r] = 0.f;

#pragma unroll
        for (int s = 0; s < 8; s++) {
            uint32_t aH[4], aL[4];
            *(uint4*)aH = *(const uint4*)&sQh[((wid * 8 + s) * 32 + aoff) * 4];
            *(uint4*)aL = *(const uint4*)&sQl[((wid * 8 + s) * 32 + aoff) * 4];
#pragma unroll
            for (int nt = 0; nt < 4; nt++) {
                uint32_t bH[2], bL[2];
                *(uint2*)bH = *(const uint2*)&sKh[((nt * 8 + s) * 32 + boff[nt]) * 2];
                *(uint2*)bL = *(const uint2*)&sKl[((nt * 8 + s) * 32 + boff[nt]) * 2];
                mma_tf32(sf[nt], aH, bH);
                mma_tf32(sf[nt], aH, bL);
                mma_tf32(sf[nt], aL, bH);
            }
        }

        // ---- online softmax (rows lane>>2, +8) ----
#pragma unroll
        for (int hf = 0; hf < 2; hf++) {
            float tm = -1e30f;
#pragma unroll
            for (int nt = 0; nt < 4; nt++)
                tm = fmaxf(tm, fmaxf(sf[nt][hf * 2], sf[nt][hf * 2 + 1]));
            tm = fmaxf(tm, __shfl_xor_sync(0xffffffffu, tm, 1));
            tm = fmaxf(tm, __shfl_xor_sync(0xffffffffu, tm, 2));
            const float mn  = fmaxf(m_run[hf], tm);
            const float fac = __expf(m_run[hf] - mn);
            float sum = 0.f;
#pragma unroll
            for (int nt = 0; nt < 4; nt++) {
#pragma unroll
                for (int j = 0; j < 2; j++) {
                    const float p = __expf(sf[nt][hf * 2 + j] - mn);
                    sf[nt][hf * 2 + j] = p;
                    sum += p;
                }
            }
            sum += __shfl_xor_sync(0xffffffffu, sum, 1);
            sum += __shfl_xor_sync(0xffffffffu, sum, 2);
            l_run[hf] = l_run[hf] * fac + sum;
            m_run[hf] = mn;
#pragma unroll
            for (int nt = 0; nt < 8; nt++) {
                oacc[nt][hf * 2]     *= fac;
                oacc[nt][hf * 2 + 1] *= fac;
            }
        }

        // ---- O += P @ V (P split in-register, shfl to A-frag layout) ----
        const int src0 = (lane & ~3) | ((lane & 3) >> 1);
        const int src2 = src0 + 2;
        const bool par = lane & 1;
#pragma unroll
        for (int s = 0; s < 4; s++) {
            uint32_t pH[4], pL[4];
#pragma unroll
            for (int r = 0; r < 4; r++) {
                pH[r] = f32_to_tf32(sf[s][r]);
                pL[r] = f32_to_tf32(sf[s][r] - __uint_as_float(pH[r]));
            }
            uint32_t aH[4], aL[4];
            {
                uint32_t u0, u1;
                u0 = __shfl_sync(0xffffffffu, pH[0], src0);
                u1 = __shfl_sync(0xffffffffu, pH[1], src0);
                aH[0] = par ? u1 : u0;
                u0 = __shfl_sync(0xffffffffu, pH[2], src0);
                u1 = __shfl_sync(0xffffffffu, pH[3], src0);
                aH[1] = par ? u1 : u0;
                u0 = __shfl_sync(0xffffffffu, pH[0], src2);
                u1 = __shfl_sync(0xffffffffu, pH[1], src2);
                aH[2] = par ? u1 : u0;
                u0 = __shfl_sync(0xffffffffu, pH[2], src2);
                u1 = __shfl_sync(0xffffffffu, pH[3], src2);
                aH[3] = par ? u1 : u0;
                u0 = __shfl_sync(0xffffffffu, pL[0], src0);
                u1 = __shfl_sync(0xffffffffu, pL[1], src0);
                aL[0] = par ? u1 : u0;
                u0 = __shfl_sync(0xffffffffu, pL[2], src0);
                u1 = __shfl_sync(0xffffffffu, pL[3], src0);
                aL[1] = par ? u1 : u0;
                u0 = __shfl_sync(0xffffffffu, pL[0], src2);
                u1 = __shfl_sync(0xffffffffu, pL[1], src2);
                aL[2] = par ? u1 : u0;
                u0 = __shfl_sync(0xffffffffu, pL[2], src2);
                u1 = __shfl_sync(0xffffffffu, pL[3], src2);
                aL[3] = par ? u1 : u0;
            }
#pragma unroll
            for (int nt = 0; nt < 8; nt++) {
                uint32_t vH[2], vL[2];
                *(uint2*)vH = *(const uint2*)&sVh[((nt * 4 + s) * 32 + voff[nt]) * 2];
                *(uint2*)vL = *(const uint2*)&sVl[((nt * 4 + s) * 32 + voff[nt]) * 2];
                mma_tf32(oacc[nt], aH, vH);
                mma_tf32(oacc[nt], aH, vL);
                mma_tf32(oacc[nt], aL, vH);
            }
        }
    }

    // ---- normalize + write ctx ----
    const float inv0 = 1.0f / l_run[0];
    const float inv1 = 1.0f / l_run[1];
    const int row0 = q0 + wid * 16 + (lane >> 2);
#pragma unroll
    for (int nt = 0; nt < 8; nt++) {
        const int col = h * HDIM + nt * 8 + 2 * (lane & 3);
        *(float2*)(ctx + ((size_t)b * SEQ + row0) * DIMS + col) =
            make_float2(oacc[nt][0] * inv0, oacc[nt][1] * inv0);
        *(float2*)(ctx + ((size_t)b * SEQ + row0 + 8) * DIMS + col) =
            make_float2(oacc[nt][2] * inv1, oacc[nt][3] * inv1);
    }
}

// ---------------------------------------------------------------------------
extern "C" void kernel_launch(void* const* d_in, const int* in_sizes, int n_in,
                              void* d_out, int out_size)
{
    const float* x      = (const float*)d_in[0];
    const float* w_qkv  = (const float*)d_in[1];
    const float* w_proj = (const float*)d_in[2];
    const float* b_proj = (const float*)d_in[3];
    float* out = (float*)d_out;

    float *qkv, *ctx, *wqkvT, *wprojT;
    cudaGetSymbolAddress((void**)&qkv, g_qkv);
    cudaGetSymbolAddress((void**)&ctx, g_ctx);
    cudaGetSymbolAddress((void**)&wqkvT, g_wqkvT);
    cudaGetSymbolAddress((void**)&wprojT, g_wprojT);

    const int M = BATCH * SEQ;

    transpose_k<<<dim3(QKVLD / 32, DIMS / 32), dim3(32, 8)>>>(w_qkv, wqkvT, DIMS, QKVLD);
    transpose_k<<<dim3(DIMS / 32, DIMS / 32), dim3(32, 8)>>>(w_proj, wprojT, DIMS, DIMS);

    gemm_mma<false><<<dim3(QKVLD / 128, M / 128), 256>>>(
        x, wqkvT, nullptr, qkv, M, QKVLD, DIMS);

    const int fsmem = 16384 * 4;   // 64 KB
    cudaFuncSetAttribute(flash_mma, cudaFuncAttributeMaxDynamicSharedMemorySize,
                         fsmem);
    flash_mma<<<dim3(SEQ / 64, NHEADS, BATCH), 128, fsmem>>>(qkv, ctx);

    gemm_mma<true><<<dim3(DIMS / 128, M / 128), 256>>>(
        ctx, wprojT, b_proj, out, M, DIMS, DIMS);
}

// round 11
// speedup vs baseline: 2.1464x; 1.2720x over previous
#include <cuda_runtime.h>
#include <cuda_bf16.h>
#include <cstdint>
#include <math.h>

#define DIMS    1024
#define SEQ     2048
#define BATCH   2
#define NHEADS  16
#define HDIM    64
#define QKVLD   3072

// ---------------------------------------------------------------------------
// Scratch (allocation-free rule: __device__ globals)
// ---------------------------------------------------------------------------
__device__ float g_qkv[(size_t)BATCH * SEQ * QKVLD];
__device__ float g_ctx[(size_t)BATCH * SEQ * DIMS];
__device__ float g_wqkvT[(size_t)QKVLD * DIMS];
__device__ float g_wprojT[(size_t)DIMS * DIMS];

__device__ __forceinline__ uint32_t f32_to_tf32(float f) {
    uint32_t u;
    asm("cvt.rna.tf32.f32 %0, %1;" : "=r"(u) : "f"(f));
    return u;
}

__device__ __forceinline__ void mma_tf32(float* d, const uint32_t* a, const uint32_t* b) {
    asm volatile(
        "mma.sync.aligned.m16n8k8.row.col.f32.tf32.tf32.f32 "
        "{%0,%1,%2,%3}, {%4,%5,%6,%7}, {%8,%9}, {%0,%1,%2,%3};"
        : "+f"(d[0]), "+f"(d[1]), "+f"(d[2]), "+f"(d[3])
        : "r"(a[0]), "r"(a[1]), "r"(a[2]), "r"(a[3]), "r"(b[0]), "r"(b[1]));
}

// bf16 m16n8k16 mma (sm_80+)
__device__ __forceinline__ void mma_bf16(float* d, const uint32_t* a, const uint32_t* b) {
    asm volatile(
        "mma.sync.aligned.m16n8k16.row.col.f32.bf16.bf16.f32 "
        "{%0,%1,%2,%3}, {%4,%5,%6,%7}, {%8,%9}, {%0,%1,%2,%3};"
        : "+f"(d[0]), "+f"(d[1]), "+f"(d[2]), "+f"(d[3])
        : "r"(a[0]), "r"(a[1]), "r"(a[2]), "r"(a[3]), "r"(b[0]), "r"(b[1]));
}

// pack two floats to bf16x2 word: low half = e (even k), high half = o (odd k).
// Intrinsic-only (no inline asm): __float22bfloat162_rn packs .x->low, .y->high.
__device__ __forceinline__ uint32_t pack2_bf16(float e, float o) {
    __nv_bfloat162 p = __float22bfloat162_rn(make_float2(e, o));
    return *reinterpret_cast<uint32_t*>(&p);
}
__device__ __forceinline__ float bf16_round(float x) {
    return __bfloat162float(__float2bfloat16_rn(x));
}

// ---------------------------------------------------------------------------
// Weight transpose (unchanged).
// ---------------------------------------------------------------------------
__global__ __launch_bounds__(256) void transpose_k(
    const float* __restrict__ in, float* __restrict__ out, int R, int C)
{
    __shared__ float t[32][33];
    int x = blockIdx.x * 32 + threadIdx.x;
    int y = blockIdx.y * 32 + threadIdx.y;
#pragma unroll
    for (int j = 0; j < 32; j += 8)
        t[threadIdx.y + j][threadIdx.x] = in[(size_t)(y + j) * C + x];
    __syncthreads();
    int x2 = blockIdx.y * 32 + threadIdx.x;
    int y2 = blockIdx.x * 32 + threadIdx.y;
#pragma unroll
    for (int j = 0; j < 32; j += 8)
        out[(size_t)(y2 + j) * R + x2] = t[threadIdx.x][threadIdx.y + j];
}

// ---------------------------------------------------------------------------
// tf32 mma.sync GEMM (unchanged — validated).
// ---------------------------------------------------------------------------
#define CH_K 16

template <bool HAS_BIAS>
__global__ __launch_bounds__(256) void gemm_mma(
    const float* __restrict__ A, const float* __restrict__ BT,
    const float* __restrict__ bias, float* __restrict__ C,
    int M, int N, int K)
{
    __shared__ uint32_t sA[2][128 * CH_K];
    __shared__ uint32_t sB[2][128 * CH_K];

    const int tid   = threadIdx.x;
    const int lane  = tid & 31;
    const int wid   = tid >> 5;
    const int warpM = wid >> 2;
    const int warpN = wid & 3;
    const int m0 = blockIdx.y * 128;
    const int n0 = blockIdx.x * 128;

    const float* agp[2];
    const float* bgp[2];
    int abase[2], bbase[2], arot[2], brot[2];
#pragma unroll
    for (int i = 0; i < 2; i++) {
        const int idx = tid + i * 256;
        const int row = idx >> 2;
        const int k0  = (idx & 3) << 2;
        agp[i] = A + (size_t)(m0 + row) * K + k0;
        {
            const int mt = row >> 4, rr = row & 15, s = k0 >> 3;
            const int bi = mt * 2 + s;
            const int reg = (rr >> 3) + 2 * ((k0 >> 2) & 1);
            arot[i]  = (bi & 1) * 2;
            abase[i] = (bi * 32 + (rr & 7) * 4) * 4 + reg;
        }
        bgp[i] = BT + (size_t)(n0 + row) * K + k0;
        {
            const int nt = row >> 3, nn = row & 7, s = k0 >> 3;
            const int bi = nt * 2 + s;
            const int reg = (k0 >> 2) & 1;
            brot[i]  = (bi & 1) * 2;
            bbase[i] = (bi * 32 + nn * 4) * 2 + reg;
        }
    }

    float acc[4][4][4];
#pragma unroll
    for (int i = 0; i < 4; i++)
#pragma unroll
        for (int j = 0; j < 4; j++)
#pragma unroll
            for (int r = 0; r < 4; r++) acc[i][j][r] = 0.f;

    float4 ra[2], rb[2];
#pragma unroll
    for (int i = 0; i < 2; i++) {
        ra[i] = *(const float4*)agp[i];
        rb[i] = *(const float4*)bgp[i];
    }
#pragma unroll
    for (int i = 0; i < 2; i++) {
        const float av[4] = {ra[i].x, ra[i].y, ra[i].z, ra[i].w};
        const float bv[4] = {rb[i].x, rb[i].y, rb[i].z, rb[i].w};
#pragma unroll
        for (int q = 0; q < 4; q++) {
            sA[0][abase[i] + ((q ^ arot[i]) << 2)] = f32_to_tf32(av[q]);
            sB[0][bbase[i] + ((q ^ brot[i]) << 1)] = f32_to_tf32(bv[q]);
        }
    }
    __syncthreads();

    const int nch = K / CH_K;
    for (int c = 0; c < nch; c++) {
        const int cur = c & 1;
        if (c + 1 < nch) {
            const int ko = (c + 1) * CH_K;
#pragma unroll
            for (int i = 0; i < 2; i++) {
                ra[i] = *(const float4*)(agp[i] + ko);
                rb[i] = *(const float4*)(bgp[i] + ko);
            }
        }

#pragma unroll
        for (int s = 0; s < 2; s++) {
            uint32_t af[4][4];
            uint32_t bf[4][2];
#pragma unroll
            for (int i = 0; i < 4; i++) {
                const int bi = (warpM * 4 + i) * 2 + s;
                const int l  = lane ^ ((bi & 1) * 2);
                *(uint4*)af[i] = *(const uint4*)&sA[cur][(bi * 32 + l) * 4];
            }
#pragma unroll
            for (int j = 0; j < 4; j++) {
                const int bi = (warpN * 4 + j) * 2 + s;
                const int l  = lane ^ ((bi & 1) * 2);
                *(uint2*)bf[j] = *(const uint2*)&sB[cur][(bi * 32 + l) * 2];
            }
#pragma unroll
            for (int i = 0; i < 4; i++)
#pragma unroll
                for (int j = 0; j < 4; j++)
                    mma_tf32(acc[i][j], af[i], bf[j]);
        }

        if (c + 1 < nch) {
            const int nxt = cur ^ 1;
#pragma unroll
            for (int i = 0; i < 2; i++) {
                const float av[4] = {ra[i].x, ra[i].y, ra[i].z, ra[i].w};
                const float bv[4] = {rb[i].x, rb[i].y, rb[i].z, rb[i].w};
#pragma unroll
                for (int q = 0; q < 4; q++) {
                    sA[nxt][abase[i] + ((q ^ arot[i]) << 2)] = f32_to_tf32(av[q]);
                    sB[nxt][bbase[i] + ((q ^ brot[i]) << 1)] = f32_to_tf32(bv[q]);
                }
            }
        }
        __syncthreads();
    }

#pragma unroll
    for (int i = 0; i < 4; i++) {
        const int row = m0 + warpM * 64 + i * 16 + (lane >> 2);
#pragma unroll
        for (int j = 0; j < 4; j++) {
            const int col = n0 + warpN * 32 + j * 8 + (lane & 3) * 2;
            float2 v0 = make_float2(acc[i][j][0], acc[i][j][1]);
            float2 v1 = make_float2(acc[i][j][2], acc[i][j][3]);
            if (HAS_BIAS) {
                const float b0 = bias[col], b1 = bias[col + 1];
                v0.x += b0; v0.y += b1;
                v1.x += b0; v1.y += b1;
            }
            *(float2*)(C + (size_t)row * N + col) = v0;
            *(float2*)(C + (size_t)(row + 8) * N + col) = v1;
        }
    }
}

// ---------------------------------------------------------------------------
// Tensor-core flash attention, split-bf16 m16n8k16, Br=64 Bc=64.
// 48 KB smem/CTA, 3 CTAs/SM, 128 threads (4 warps, warp = 16 q-rows).
// x = bf16(x) + bf16(x - bf16(x)); products hh+hl+lh -> ~1e-5 rel error.
// SMEM word layouts (bf16x2 words, k-pairs packed; 32-slot fragment blocks):
//   A (Q, 64x64): bi = mt*4 + s16 (s16 = k>>4), 16 blocks x 32 slots x 4 regs
//       slot(r,k) = ((r&7)<<2) | ((((k&15)>>1)&3) ^ (((r&7)>>1)&3))
//       reg = ((r>>3)&1) + 2*(((k&15)>>3)&1), word-half = k&1
//   B (K: n=kv,k=hd; V: n=hd,k=kv): bi = nt*4 + s16, 32 blocks x 32 slots x 2
//       reg = ((k&15)>>3)&1
//   rot(bi) = (((bi>>3)&1)<<2) | (((bi>>4)&1)<<3), XORed into slot.
// P(C-frag fp32) -> bf16 A-frag by packing (c0,c1)/(c2,c3) of adjacent
// n8-tiles — no shuffles, no smem round-trip.
// ---------------------------------------------------------------------------
__global__ __launch_bounds__(128, 3) void flash_mma(
    const float* __restrict__ qkv, float* __restrict__ ctx)
{
    extern __shared__ uint32_t fsm[];
    uint32_t* sQh = fsm;             // 2048 words
    uint32_t* sQl = fsm + 2048;
    uint32_t* sKh = fsm + 4096;
    uint32_t* sKl = fsm + 6144;
    uint32_t* sVh = fsm + 8192;
    uint32_t* sVl = fsm + 10240;     // total 12288 words = 48 KB

    const int tid  = threadIdx.x;
    const int lane = tid & 31;
    const int wid  = tid >> 5;
    const int b = blockIdx.z, h = blockIdx.y;
    const int q0 = blockIdx.x * 64;

    const float* Qg = qkv + (size_t)b * SEQ * QKVLD + h * HDIM;
    const float* Kg = Qg + DIMS;
    const float* Vg = Qg + 2 * DIMS;

    const int slotC = ((lane >> 2) << 2) | ((lane & 3) ^ ((lane >> 3) & 3));
    // A (Q): bi = wid*4 + s, s<4 -> bi>>3 = wid>>1, bi>>4 = 0
    const int aoff = slotC ^ (((wid >> 1) & 1) << 2);
    // B (K and V): bi = nt*4 + s -> bi>>3 = nt>>1, bi>>4 = nt>>2
    int boff[8];
#pragma unroll
    for (int nt = 0; nt < 8; nt++)
        boff[nt] = slotC ^ ((((nt >> 1) & 1) << 2) | (((nt >> 2) & 1) << 3));

    // ---- stage Q (scaled 0.125, hi/lo bf16) : 1024 float4, 8/thread ----
#pragma unroll
    for (int i = 0; i < 8; i++) {
        const int idx = tid + i * 128;
        const int row = idx & 63, k0 = (idx >> 6) * 4;
        float4 v = *(const float4*)(Qg + (size_t)(q0 + row) * QKVLD + k0);
        const float x0 = v.x * 0.125f, x1 = v.y * 0.125f;
        const float x2 = v.z * 0.125f, x3 = v.w * 0.125f;
        const int bi = (row >> 4) * 4 + (k0 >> 4);
        const int rot = (((bi >> 3) & 1) << 2) | (((bi >> 4) & 1) << 3);
        const int scr = ((row & 7) >> 1) & 3;
        const int p0 = (k0 >> 1) & 3;                 // in {0,2}
        const int reg = ((row >> 3) & 1) + 2 * ((k0 >> 3) & 1);
        const int s0 = (((row & 7) << 2) | (p0 ^ scr)) ^ rot;
        const int s1 = (((row & 7) << 2) | ((p0 + 1) ^ scr)) ^ rot;
        const int a0 = (bi * 32 + s0) * 4 + reg;
        const int a1 = (bi * 32 + s1) * 4 + reg;
        sQh[a0] = pack2_bf16(x0, x1);
        sQh[a1] = pack2_bf16(x2, x3);
        sQl[a0] = pack2_bf16(x0 - bf16_round(x0), x1 - bf16_round(x1));
        sQl[a1] = pack2_bf16(x2 - bf16_round(x2), x3 - bf16_round(x3));
    }

    float oacc[8][4];
    float m_run[2], l_run[2];
#pragma unroll
    for (int nt = 0; nt < 8; nt++)
#pragma unroll
        for (int r = 0; r < 4; r++) oacc[nt][r] = 0.f;
    m_run[0] = m_run[1] = -1e30f;
    l_run[0] = l_run[1] = 0.f;

    for (int kv0 = 0; kv0 < SEQ; kv0 += 64) {
        __syncthreads();   // prior iter done with sK/sV (covers Q stage, iter 0)

        // ---- stage K: 64 kv x 64 hd, B-layout (n=kv, k=hd), 8 f4/thread ----
#pragma unroll
        for (int i = 0; i < 8; i++) {
            const int idx = tid + i * 128;
            const int n = idx & 63, k0 = (idx >> 6) * 4;
            float4 v = *(const float4*)(Kg + (size_t)(kv0 + n) * QKVLD + k0);
            const int bi = (n >> 3) * 4 + (k0 >> 4);
            const int rot = (((bi >> 3) & 1) << 2) | (((bi >> 4) & 1) << 3);
            const int scr = ((n & 7) >> 1) & 3;
            const int p0 = (k0 >> 1) & 3;
            const int reg = (k0 >> 3) & 1;
            const int s0 = (((n & 7) << 2) | (p0 ^ scr)) ^ rot;
            const int s1 = (((n & 7) << 2) | ((p0 + 1) ^ scr)) ^ rot;
            const int a0 = (bi * 32 + s0) * 2 + reg;
            const int a1 = (bi * 32 + s1) * 2 + reg;
            sKh[a0] = pack2_bf16(v.x, v.y);
            sKh[a1] = pack2_bf16(v.z, v.w);
            sKl[a0] = pack2_bf16(v.x - bf16_round(v.x), v.y - bf16_round(v.y));
            sKl[a1] = pack2_bf16(v.z - bf16_round(v.z), v.w - bf16_round(v.w));
        }
        // ---- stage V: B-layout (n=hd, k=kv); pack kv-pairs; 4 groups/thread ----
#pragma unroll
        for (int i = 0; i < 4; i++) {
            const int idx = tid + i * 128;          // 0..511
            const int hd4 = idx & 15, kvp = idx >> 4;
            const int kvr = kvp * 2;                // even kv row
            float4 ve = *(const float4*)(Vg + (size_t)(kv0 + kvr) * QKVLD + hd4 * 4);
            float4 vo = *(const float4*)(Vg + (size_t)(kv0 + kvr + 1) * QKVLD + hd4 * 4);
            const float es[4] = {ve.x, ve.y, ve.z, ve.w};
            const float os[4] = {vo.x, vo.y, vo.z, vo.w};
            const int pp  = (kvr >> 1) & 3;
            const int reg = (kvr >> 3) & 1;
#pragma unroll
            for (int q = 0; q < 4; q++) {
                const int n = hd4 * 4 + q;
                const int bi = (n >> 3) * 4 + (kvr >> 4);
                const int rot = (((bi >> 3) & 1) << 2) | (((bi >> 4) & 1) << 3);
                const int scr = ((n & 7) >> 1) & 3;
                const int sl = (((n & 7) << 2) | (pp ^ scr)) ^ rot;
                const int a = (bi * 32 + sl) * 2 + reg;
                sVh[a] = pack2_bf16(es[q], os[q]);
                sVl[a] = pack2_bf16(es[q] - bf16_round(es[q]),
                                    os[q] - bf16_round(os[q]));
            }
        }
        __syncthreads();

        // ---- S = (Q*scale) @ K^T : 4 k16-steps x 8 kv-tiles, 3-term ----
        float sf[8][4];
#pragma unroll
        for (int nt = 0; nt < 8; nt++)
#pragma unroll
            for (int r = 0; r < 4; r++) sf[nt][r] = 0.f;

#pragma unroll
        for (int s = 0; s < 4; s++) {
            uint32_t aH[4], aL[4];
            *(uint4*)aH = *(const uint4*)&sQh[((wid * 4 + s) * 32 + aoff) * 4];
            *(uint4*)aL = *(const uint4*)&sQl[((wid * 4 + s) * 32 + aoff) * 4];
#pragma unroll
            for (int nt = 0; nt < 8; nt++) {
                uint32_t bH[2], bL[2];
                *(uint2*)bH = *(const uint2*)&sKh[((nt * 4 + s) * 32 + boff[nt]) * 2];
                *(uint2*)bL = *(const uint2*)&sKl[((nt * 4 + s) * 32 + boff[nt]) * 2];
                mma_bf16(sf[nt], aH, bH);
                mma_bf16(sf[nt], aH, bL);
                mma_bf16(sf[nt], aL, bH);
            }
        }

        // ---- online softmax (rows lane>>2, +8) ----
#pragma unroll
        for (int hf = 0; hf < 2; hf++) {
            float tm = -1e30f;
#pragma unroll
            for (int nt = 0; nt < 8; nt++)
                tm = fmaxf(tm, fmaxf(sf[nt][hf * 2], sf[nt][hf * 2 + 1]));
            tm = fmaxf(tm, __shfl_xor_sync(0xffffffffu, tm, 1));
            tm = fmaxf(tm, __shfl_xor_sync(0xffffffffu, tm, 2));
            const float mn  = fmaxf(m_run[hf], tm);
            const float fac = __expf(m_run[hf] - mn);
            float sum = 0.f;
#pragma unroll
            for (int nt = 0; nt < 8; nt++) {
#pragma unroll
                for (int j = 0; j < 2; j++) {
                    const float p = __expf(sf[nt][hf * 2 + j] - mn);
                    sf[nt][hf * 2 + j] = p;
                    sum += p;
                }
            }
            sum += __shfl_xor_sync(0xffffffffu, sum, 1);
            sum += __shfl_xor_sync(0xffffffffu, sum, 2);
            l_run[hf] = l_run[hf] * fac + sum;
            m_run[hf] = mn;
#pragma unroll
            for (int nt = 0; nt < 8; nt++) {
                oacc[nt][hf * 2]     *= fac;
                oacc[nt][hf * 2 + 1] *= fac;
            }
        }

        // ---- O += P @ V: P C-frag -> bf16 A-frag by packing (no shfl) ----
#pragma unroll
        for (int s = 0; s < 4; s++) {
            const float* p0 = sf[2 * s];
            const float* p1 = sf[2 * s + 1];
            uint32_t aH[4], aL[4];
            aH[0] = pack2_bf16(p0[0], p0[1]);
            aH[1] = pack2_bf16(p0[2], p0[3]);
            aH[2] = pack2_bf16(p1[0], p1[1]);
            aH[3] = pack2_bf16(p1[2], p1[3]);
            aL[0] = pack2_bf16(p0[0] - bf16_round(p0[0]), p0[1] - bf16_round(p0[1]));
            aL[1] = pack2_bf16(p0[2] - bf16_round(p0[2]), p0[3] - bf16_round(p0[3]));
            aL[2] = pack2_bf16(p1[0] - bf16_round(p1[0]), p1[1] - bf16_round(p1[1]));
            aL[3] = pack2_bf16(p1[2] - bf16_round(p1[2]), p1[3] - bf16_round(p1[3]));
#pragma unroll
            for (int nt = 0; nt < 8; nt++) {
                uint32_t vH[2], vL[2];
                *(uint2*)vH = *(const uint2*)&sVh[((nt * 4 + s) * 32 + boff[nt]) * 2];
                *(uint2*)vL = *(const uint2*)&sVl[((nt * 4 + s) * 32 + boff[nt]) * 2];
                mma_bf16(oacc[nt], aH, vH);
                mma_bf16(oacc[nt], aH, vL);
                mma_bf16(oacc[nt], aL, vH);
            }
        }
    }

    // ---- normalize + write ctx[b][q][h*64 + d] ----
    const float inv0 = 1.0f / l_run[0];
    const float inv1 = 1.0f / l_run[1];
    const int row0 = q0 + wid * 16 + (lane >> 2);
#pragma unroll
    for (int nt = 0; nt < 8; nt++) {
        const int col = h * HDIM + nt * 8 + 2 * (lane & 3);
        *(float2*)(ctx + ((size_t)b * SEQ + row0) * DIMS + col) =
            make_float2(oacc[nt][0] * inv0, oacc[nt][1] * inv0);
        *(float2*)(ctx + ((size_t)b * SEQ + row0 + 8) * DIMS + col) =
            make_float2(oacc[nt][2] * inv1, oacc[nt][3] * inv1);
    }
}

// ---------------------------------------------------------------------------
extern "C" void kernel_launch(void* const* d_in, const int* in_sizes, int n_in,
                              void* d_out, int out_size)
{
    const float* x      = (const float*)d_in[0];
    const float* w_qkv  = (const float*)d_in[1];
    const float* w_proj = (const float*)d_in[2];
    const float* b_proj = (const float*)d_in[3];
    float* out = (float*)d_out;

    float *qkv, *ctx, *wqkvT, *wprojT;
    cudaGetSymbolAddress((void**)&qkv, g_qkv);
    cudaGetSymbolAddress((void**)&ctx, g_ctx);
    cudaGetSymbolAddress((void**)&wqkvT, g_wqkvT);
    cudaGetSymbolAddress((void**)&wprojT, g_wprojT);

    const int M = BATCH * SEQ;

    transpose_k<<<dim3(QKVLD / 32, DIMS / 32), dim3(32, 8)>>>(w_qkv, wqkvT, DIMS, QKVLD);
    transpose_k<<<dim3(DIMS / 32, DIMS / 32), dim3(32, 8)>>>(w_proj, wprojT, DIMS, DIMS);

    gemm_mma<false><<<dim3(QKVLD / 128, M / 128), 256>>>(
        x, wqkvT, nullptr, qkv, M, QKVLD, DIMS);

    const int fsmem = 12288 * 4;   // 48 KB
    cudaFuncSetAttribute(flash_mma, cudaFuncAttributeMaxDynamicSharedMemorySize,
                         fsmem);
    flash_mma<<<dim3(SEQ / 64, NHEADS, BATCH), 128, fsmem>>>(qkv, ctx);

    gemm_mma<true><<<dim3(DIMS / 128, M / 128), 256>>>(
        ctx, wprojT, b_proj, out, M, DIMS, DIMS);
}